// round 1
// baseline (speedup 1.0000x reference)
#include <cuda_runtime.h>
#include <float.h>

// Problem constants
#define B_  32
#define D_  3
#define T_  16384
#define S_  128
#define L_  16
#define H_  512
#define C_  10
#define TP  16369      // T - L + 1 valid window positions
#define SHN 48         // D*L shapelet elements

// Scratch: window_square precomputed once (reused by all 128 shapelet blocks)
__device__ float g_wsq[B_ * T_];

// ---------------------------------------------------------------------------
// Kernel A: wsq[b][t] = sum_{d,l} x[b][d][t+l]^2
// ---------------------------------------------------------------------------
__global__ void wsq_kernel(const float* __restrict__ x) {
    int t = blockIdx.x * blockDim.x + threadIdx.x;
    int b = blockIdx.y;
    if (t >= TP) return;
    const float* xb = x + b * D_ * T_;
    float s = 0.f;
    #pragma unroll
    for (int d = 0; d < D_; ++d) {
        const float* xr = xb + d * T_ + t;
        #pragma unroll
        for (int l = 0; l < L_; ++l) {
            float v = __ldg(xr + l);
            s = fmaf(v, v, s);
        }
    }
    g_wsq[b * T_ + t] = s;
}

// ---------------------------------------------------------------------------
// Kernel B: per (b, s) block — cross-correlation + min over positions
// ---------------------------------------------------------------------------
#define TILE 2048
#define POS  8
#define ROW  (TILE + 16)   // 2064 floats per smem row (window overreach)

__global__ __launch_bounds__(256, 2) void dist_kernel(
    const float* __restrict__ x,
    const float* __restrict__ sh_g,
    float* __restrict__ out_dist)
{
    __shared__ float sx[D_][ROW];
    __shared__ float red[256];

    const int s = blockIdx.x;
    const int b = blockIdx.y;
    const int tid = threadIdx.x;

    // Shapelet into registers (uniform across block) + its squared norm
    float sh[SHN];
    float ssq = 0.f;
    const float* shp = sh_g + s * SHN;
    #pragma unroll
    for (int i = 0; i < SHN; ++i) {
        sh[i] = __ldg(shp + i);
        ssq = fmaf(sh[i], sh[i], ssq);
    }

    const float* xb = x + b * D_ * T_;
    const float* wq = g_wsq + b * T_;

    float dmin = FLT_MAX;

    for (int tile = 0; tile < T_ / TILE; ++tile) {
        const int tbase = tile * TILE;

        // Cooperative tile load (float4, coalesced), zero-pad past end of x
        #pragma unroll
        for (int d = 0; d < D_; ++d) {
            for (int j = tid * 4; j < ROW; j += 256 * 4) {
                float4 v;
                int e = tbase + j;
                if (e + 3 < T_) {
                    v = *reinterpret_cast<const float4*>(xb + d * T_ + e);
                } else {
                    v.x = (e     < T_) ? xb[d*T_ + e]     : 0.f;
                    v.y = (e + 1 < T_) ? xb[d*T_ + e + 1] : 0.f;
                    v.z = (e + 2 < T_) ? xb[d*T_ + e + 2] : 0.f;
                    v.w = (e + 3 < T_) ? xb[d*T_ + e + 3] : 0.f;
                }
                *reinterpret_cast<float4*>(&sx[d][j]) = v;
            }
        }
        __syncthreads();

        const int base = tid * POS;   // 8 contiguous positions per thread
        float acc[POS];
        #pragma unroll
        for (int p = 0; p < POS; ++p) acc[p] = 0.f;

        #pragma unroll
        for (int d = 0; d < D_; ++d) {
            // Register window: 24 floats via 6 conflict-free LDS.128
            float w[POS + L_];
            #pragma unroll
            for (int q = 0; q < (POS + L_) / 4; ++q)
                *reinterpret_cast<float4*>(&w[q * 4]) =
                    *reinterpret_cast<const float4*>(&sx[d][base + q * 4]);
            #pragma unroll
            for (int l = 0; l < L_; ++l) {
                const float sv = sh[d * L_ + l];
                #pragma unroll
                for (int p = 0; p < POS; ++p)
                    acc[p] = fmaf(sv, w[p + l], acc[p]);
            }
        }

        #pragma unroll
        for (int p = 0; p < POS; ++p) {
            const int t = tbase + base + p;          // always < T_ (safe load)
            const float dist = wq[t] + ssq - 2.f * acc[p];
            if (t < TP) dmin = fminf(dmin, dist);
        }
        __syncthreads();
    }

    // Block min reduction
    red[tid] = dmin;
    __syncthreads();
    #pragma unroll
    for (int off = 128; off > 0; off >>= 1) {
        if (tid < off) red[tid] = fminf(red[tid], red[tid + off]);
        __syncthreads();
    }
    if (tid == 0) out_dist[b * S_ + s] = red[0];
}

// ---------------------------------------------------------------------------
// Kernel C: fused MLP  (distance @ W1^T + b1) -> relu -> @ W2^T + b2
// ---------------------------------------------------------------------------
__global__ void mlp_kernel(const float* __restrict__ dist,
                           const float* __restrict__ W1,
                           const float* __restrict__ b1,
                           const float* __restrict__ W2,
                           const float* __restrict__ b2,
                           float* __restrict__ out_cls)
{
    __shared__ float ds[S_];
    __shared__ float hs[H_];
    const int b = blockIdx.x;
    const int tid = threadIdx.x;     // 512 threads

    if (tid < S_) ds[tid] = dist[b * S_ + tid];
    __syncthreads();

    {   // hidden layer: thread tid owns neuron tid
        float acc = b1[tid];
        const float* w = W1 + tid * S_;
        #pragma unroll 8
        for (int s2 = 0; s2 < S_; ++s2) acc = fmaf(ds[s2], w[s2], acc);
        hs[tid] = fmaxf(acc, 0.f);
    }
    __syncthreads();

    const int warp = tid >> 5, lane = tid & 31;
    if (warp < C_) {   // warp w computes class w
        const float* w = W2 + warp * H_;
        float acc = 0.f;
        #pragma unroll
        for (int j = lane; j < H_; j += 32) acc = fmaf(hs[j], w[j], acc);
        #pragma unroll
        for (int off = 16; off > 0; off >>= 1)
            acc += __shfl_down_sync(0xffffffffu, acc, off);
        if (lane == 0) out_cls[b * C_ + warp] = acc + b2[warp];
    }
}

// ---------------------------------------------------------------------------
extern "C" void kernel_launch(void* const* d_in, const int* in_sizes, int n_in,
                              void* d_out, int out_size)
{
    const float* x  = (const float*)d_in[0];  // (32, 3, 16384)
    const float* sh = (const float*)d_in[1];  // (128, 1, 3, 16)
    const float* W1 = (const float*)d_in[2];  // (512, 128)
    const float* b1 = (const float*)d_in[3];  // (512,)
    const float* W2 = (const float*)d_in[4];  // (10, 512)
    const float* b2 = (const float*)d_in[5];  // (10,)

    float* out_dist = (float*)d_out;               // (32, 128) = 4096
    float* out_cls  = (float*)d_out + B_ * S_;     // (32, 10)  = 320

    // A: window squares
    {
        dim3 grid((TP + 255) / 256, B_);
        wsq_kernel<<<grid, 256>>>(x);
    }
    // B: shapelet distances
    {
        dim3 grid(S_, B_);
        dist_kernel<<<grid, 256>>>(x, sh, out_dist);
    }
    // C: MLP
    mlp_kernel<<<B_, H_>>>(out_dist, W1, b1, W2, b2, out_cls);
}

// round 3
// speedup vs baseline: 4.9422x; 4.9422x over previous
#include <cuda_runtime.h>
#include <cstdint>

// ---------------------------------------------------------------------------
// Problem constants
// ---------------------------------------------------------------------------
#define B_  32
#define D_  3
#define T_  16384
#define S_  128
#define L_  16
#define H_  512
#define C_  10
#define TP  16369          // T - L + 1 valid positions
#define SHN 48             // D*L  (= K, divisible by 8: 6 k-steps)

#define NT      128        // positions per block tile (GEMM N-tile)
#define NTILES  (B_ * (T_ / NT))   // 4096
#define THR     256
#define GRID    296        // 2 blocks / SM
#define ASTRIDE 52         // A smem row stride (floats) — conflict-free
#define XT_W    (NT + L_)  // 144 floats per x row in smem

#define INF_F __int_as_float(0x7F800000)

// ---------------------------------------------------------------------------
__device__ __forceinline__ float tf32r(float f) {
    uint32_t u;
    asm("cvt.rna.tf32.f32 %0, %1;" : "=r"(u) : "f"(f));
    return __uint_as_float(u);
}

// D += A(16x8,row) * B(8x8,col)   tf32 -> f32
__device__ __forceinline__ void mma8(float* d, uint32_t a0, uint32_t a1,
                                     uint32_t a2, uint32_t a3,
                                     uint32_t b0, uint32_t b1) {
    asm volatile(
        "mma.sync.aligned.m16n8k8.row.col.f32.tf32.tf32.f32 "
        "{%0,%1,%2,%3}, {%4,%5,%6,%7}, {%8,%9}, {%0,%1,%2,%3};"
        : "+f"(d[0]), "+f"(d[1]), "+f"(d[2]), "+f"(d[3])
        : "r"(a0), "r"(a1), "r"(a2), "r"(a3), "r"(b0), "r"(b1));
}

// ---------------------------------------------------------------------------
// Kernel 0: init distances to +inf
// ---------------------------------------------------------------------------
__global__ void init_kernel(float* out_dist) {
    int i = blockIdx.x * blockDim.x + threadIdx.x;
    if (i < B_ * S_) reinterpret_cast<int*>(out_dist)[i] = 0x7F800000;
}

// ---------------------------------------------------------------------------
// Kernel 1: persistent tf32-MMA shapelet distance
//   A (smem, [128 x 48] stride 52) = -2 * tf32(shapelet)
//   B = sliding windows, read in-place from tf32-rounded x tile
//   D = -2*corr ; dist = min_n (D + wsq[n]) + ssq[m]
// ---------------------------------------------------------------------------
__global__ __launch_bounds__(THR, 2) void dist_kernel(
    const float* __restrict__ x,
    const float* __restrict__ shg,
    float* __restrict__ out_dist)
{
    __shared__ float sA[S_ * ASTRIDE];      // 26624 B
    __shared__ float xs[D_ * XT_W];         // raw, then tf32-rounded in place
    __shared__ float swsq[NT];
    __shared__ float sssq[S_];
    __shared__ int   sdmin[S_];

    const int tid  = threadIdx.x;
    const int wid  = tid >> 5;
    const int lane = tid & 31;
    const int q    = lane >> 2;      // groupID
    const int r    = lane & 3;       // threadID_in_group

    // --- one-time: load shapelets as -2*tf32(a); exact fp32 squared norms ---
    for (int idx = tid; idx < S_ * SHN; idx += THR) {
        const int m = idx / SHN, k = idx - m * SHN;
        sA[m * ASTRIDE + k] = tf32r(shg[idx]) * -2.0f;
    }
    if (tid < S_) {
        const float* srow = shg + tid * SHN;
        float ssq = 0.f;
        #pragma unroll
        for (int k = 0; k < SHN; ++k) ssq = fmaf(srow[k], srow[k], ssq);
        sssq[tid] = ssq;
    }
    __syncthreads();

    const int mbase = (wid & 3) * 32;       // warp's 32 M-rows
    const int nbase = (wid >> 2) * 64;      // warp's 64 N-cols

    for (int tile = blockIdx.x; tile < NTILES; tile += GRID) {
        const int b     = tile >> 7;                     // 128 tiles / batch
        const int tbase = (tile & 127) * NT;
        const float* xb = x + (size_t)b * D_ * T_;

        // reset per-tile min + load raw x tile (zero-pad past T)
        if (tid < S_) sdmin[tid] = 0x7F800000;
        #pragma unroll
        for (int i = tid; i < D_ * XT_W; i += THR) {
            const int d = i / XT_W, j = i - d * XT_W;
            const int g = tbase + j;
            xs[i] = (g < T_) ? xb[d * T_ + g] : 0.f;
        }
        __syncthreads();

        // window squares from RAW x (exact); poison invalid tail positions
        if (tid < NT) {
            float wacc = 0.f;
            #pragma unroll
            for (int d = 0; d < D_; ++d) {
                #pragma unroll
                for (int l = 0; l < L_; ++l) {
                    const float v = xs[d * XT_W + tid + l];
                    wacc = fmaf(v, v, wacc);
                }
            }
            swsq[tid] = (tbase + tid < TP) ? wacc : INF_F;
        }
        __syncthreads();

        // round x tile to tf32 in place
        #pragma unroll
        for (int i = tid; i < D_ * XT_W; i += THR) xs[i] = tf32r(xs[i]);
        __syncthreads();

        // ===== MMA: acc[mt][nt][4], warp tile 32M x 64N, K=48 =====
        float acc[2][8][4];
        #pragma unroll
        for (int mt = 0; mt < 2; ++mt)
            #pragma unroll
            for (int nt = 0; nt < 8; ++nt)
                #pragma unroll
                for (int e = 0; e < 4; ++e) acc[mt][nt][e] = 0.f;

        const uint32_t* sAu = reinterpret_cast<const uint32_t*>(sA);
        const uint32_t* xsu = reinterpret_cast<const uint32_t*>(xs);

        #pragma unroll
        for (int ks = 0; ks < 6; ++ks) {
            const int d  = ks >> 1;
            const int l0 = (ks & 1) * 8;
            const int kc = ks * 8 + r;

            uint32_t a[2][4];
            #pragma unroll
            for (int mt = 0; mt < 2; ++mt) {
                const int rowb = mbase + mt * 16;
                a[mt][0] = sAu[(rowb + q    ) * ASTRIDE + kc    ];
                a[mt][1] = sAu[(rowb + q + 8) * ASTRIDE + kc    ];
                a[mt][2] = sAu[(rowb + q    ) * ASTRIDE + kc + 4];
                a[mt][3] = sAu[(rowb + q + 8) * ASTRIDE + kc + 4];
            }
            const uint32_t* xr = xsu + d * XT_W + l0 + r;
            #pragma unroll
            for (int nt = 0; nt < 8; ++nt) {
                const int n = nbase + nt * 8 + q;
                const uint32_t b0 = xr[n];
                const uint32_t b1 = xr[n + 4];
                mma8(acc[0][nt], a[0][0], a[0][1], a[0][2], a[0][3], b0, b1);
                mma8(acc[1][nt], a[1][0], a[1][1], a[1][2], a[1][3], b0, b1);
            }
        }

        // ===== epilogue: dist = min_n(acc + wsq[n]) + ssq[m] =====
        float wq[8][2];
        #pragma unroll
        for (int nt = 0; nt < 8; ++nt) {
            wq[nt][0] = swsq[nbase + nt * 8 + r * 2    ];
            wq[nt][1] = swsq[nbase + nt * 8 + r * 2 + 1];
        }
        // rows handled by this thread: mbase + mt*16 + h*8 + q
        float rmin[2][2];
        #pragma unroll
        for (int mt = 0; mt < 2; ++mt)
            #pragma unroll
            for (int h = 0; h < 2; ++h) {
                float m = INF_F;
                #pragma unroll
                for (int nt = 0; nt < 8; ++nt) {
                    m = fminf(m, acc[mt][nt][h * 2    ] + wq[nt][0]);
                    m = fminf(m, acc[mt][nt][h * 2 + 1] + wq[nt][1]);
                }
                rmin[mt][h] = m;
            }
        // quad reduce (lanes sharing q hold the same rows)
        #pragma unroll
        for (int mt = 0; mt < 2; ++mt)
            #pragma unroll
            for (int h = 0; h < 2; ++h) {
                float v = rmin[mt][h];
                v = fminf(v, __shfl_xor_sync(0xffffffffu, v, 1));
                v = fminf(v, __shfl_xor_sync(0xffffffffu, v, 2));
                rmin[mt][h] = v;
            }
        if (r == 0) {
            #pragma unroll
            for (int mt = 0; mt < 2; ++mt)
                #pragma unroll
                for (int h = 0; h < 2; ++h) {
                    const int row = mbase + mt * 16 + h * 8 + q;
                    const float v = rmin[mt][h] + sssq[row];
                    atomicMin(&sdmin[row], __float_as_int(v));
                }
        }
        __syncthreads();

        if (tid < S_)
            atomicMin(reinterpret_cast<int*>(out_dist) + b * S_ + tid, sdmin[tid]);
        __syncthreads();
    }
}

// ---------------------------------------------------------------------------
// Kernel 2: fused MLP
// ---------------------------------------------------------------------------
__global__ void mlp_kernel(const float* __restrict__ dist,
                           const float* __restrict__ W1,
                           const float* __restrict__ b1,
                           const float* __restrict__ W2,
                           const float* __restrict__ b2,
                           float* __restrict__ out_cls)
{
    __shared__ float ds[S_];
    __shared__ float hs[H_];
    const int b = blockIdx.x;
    const int tid = threadIdx.x;   // 512

    if (tid < S_) ds[tid] = dist[b * S_ + tid];
    __syncthreads();

    {
        float acc = b1[tid];
        const float* w = W1 + tid * S_;
        #pragma unroll 8
        for (int s2 = 0; s2 < S_; ++s2) acc = fmaf(ds[s2], w[s2], acc);
        hs[tid] = fmaxf(acc, 0.f);
    }
    __syncthreads();

    const int warp = tid >> 5, lane = tid & 31;
    if (warp < C_) {
        const float* w = W2 + warp * H_;
        float acc = 0.f;
        #pragma unroll
        for (int j = lane; j < H_; j += 32) acc = fmaf(hs[j], w[j], acc);
        #pragma unroll
        for (int off = 16; off > 0; off >>= 1)
            acc += __shfl_down_sync(0xffffffffu, acc, off);
        if (lane == 0) out_cls[b * C_ + warp] = acc + b2[warp];
    }
}

// ---------------------------------------------------------------------------
extern "C" void kernel_launch(void* const* d_in, const int* in_sizes, int n_in,
                              void* d_out, int out_size)
{
    const float* x  = (const float*)d_in[0];
    const float* sh = (const float*)d_in[1];
    const float* W1 = (const float*)d_in[2];
    const float* b1 = (const float*)d_in[3];
    const float* W2 = (const float*)d_in[4];
    const float* b2 = (const float*)d_in[5];

    float* out_dist = (float*)d_out;
    float* out_cls  = (float*)d_out + B_ * S_;

    init_kernel<<<(B_ * S_ + 255) / 256, 256>>>(out_dist);
    dist_kernel<<<GRID, THR>>>(x, sh, out_dist);
    mlp_kernel<<<B_, H_>>>(out_dist, W1, b1, W2, b2, out_cls);
}